// round 15
// baseline (speedup 1.0000x reference)
#include <cuda_runtime.h>

#define HH 1024
#define WW 1024
#define NPTS 128
#define NBLK 32
#define PPB 4             // points per block
#define TPB 512           // 4 points x 128 row-slots
#define BIGD 16384        // sentinel 1D distance
#define INF_I 0x3FFFFFFF
#define INF_B (1 << 20)

// Cross-block handoff: one float + one flag per block, each on its own 128B line.
__device__ volatile float g_part[NBLK * 32];
__device__ volatile int   g_flag[NBLK * 32];   // zero-init; block 0 resets each run

// Exact nearest on/off column distance in row `rowf` from query col pc.
// 8-col preloaded window + lazy aligned extension (L == 3 mod 4, R == 0 mod 4).
__device__ __forceinline__ void scan_cols(const float* __restrict__ rowf,
                                          int pc, int c0, int &don, int &doff) {
    float4 a = *reinterpret_cast<const float4*>(rowf + c0);
    float4 b = *reinterpret_cast<const float4*>(rowf + c0 + 4);
    don = BIGD; doff = BIGD;
    {
        float w[8] = {a.x, a.y, a.z, a.w, b.x, b.y, b.z, b.w};
        #pragma unroll
        for (int t = 0; t < 8; t++) {
            int d = abs(c0 + t - pc);
            if (w[t] != 0.0f) don = min(don, d); else doff = min(doff, d);
        }
    }
    int L = c0 - 1;
    int R = c0 + 8;
    #pragma unroll 1
    while (true) {
        int bl = (L >= 0) ? (pc - L) : INF_I;
        int br = (R < WW) ? (R - pc) : INF_I;
        int bound = min(bl, br);
        if (don <= bound && doff <= bound) break;    // certain once both exhausted
        if (bl <= br) {
            float4 v = *reinterpret_cast<const float4*>(rowf + (L - 3));
            float u[4] = {v.x, v.y, v.z, v.w};
            #pragma unroll
            for (int t = 0; t < 4; t++) {
                int d = pc - (L - 3 + t);
                if (u[t] != 0.0f) don = min(don, d); else doff = min(doff, d);
            }
            L -= 4;
        } else {
            float4 v = *reinterpret_cast<const float4*>(rowf + R);
            float u[4] = {v.x, v.y, v.z, v.w};
            #pragma unroll
            for (int t = 0; t < 4; t++) {
                int d = (R + t) - pc;
                if (u[t] != 0.0f) don = min(don, d); else doff = min(doff, d);
            }
            R += 4;
        }
    }
}

__global__ void __launch_bounds__(TPB, 1)
roadloss_kernel(const float* __restrict__ hd,
                const int*   __restrict__ pred,
                float*       __restrict__ out) {
    int tid  = threadIdx.x;
    int b    = blockIdx.x;
    int pn   = tid >> 7;          // local point 0..3
    int slot = tid & 127;         // row slot 0..127 -> offset slot-64
    int gpt  = b * PPB + pn;      // global point

    int2 p = reinterpret_cast<const int2*>(pred)[gpt];
    int pr = p.x;                 // vs rows in d2
    int pc = p.y;                 // vs cols in d2

    // Loss-neighbor prefetch for this block's 4 points (tid<4, one each).
    // Reference indexes hd_map[py-1..py, px-1..px] with px=pred[:,0],
    // py=pred[:,1] (roles swapped vs distance), JAX-clamped.
    float nv0 = 0.f, nv1 = 0.f, nv2 = 0.f, nv3 = 0.f;
    int2 pl = make_int2(0, 0);
    if (tid < PPB) {
        pl = reinterpret_cast<const int2*>(pred)[b * PPB + tid];
        int px = pl.x, py = pl.y;
        int r0 = min(max(py - 1, 0), HH - 1);
        int r1 = min(max(py,     0), HH - 1);
        int cA = min(max(px - 1, 0), WW - 1);
        int cB = min(max(px,     0), WW - 1);
        nv0 = hd[r0 * WW + cA];
        nv1 = hd[r0 * WW + cB];
        nv2 = hd[r1 * WW + cA];
        nv3 = hd[r1 * WW + cB];
    }

    int c0 = (pc - 4) & ~3;
    if (c0 < 0) c0 = 0;
    if (c0 > WW - 8) c0 = WW - 8;

    // ---- Single round: offsets -64..63, one row per thread ----
    int off = slot - 64;
    int r   = pr + off;
    int von = INF_I, voff = INF_I;
    if (r >= 0 && r < HH) {
        int dn, df;
        scan_cols(hd + r * WW, pc, c0, dn, df);
        von  = off * off + dn * dn;      // exact in int
        voff = off * off + df * df;
    }
    von  = __reduce_min_sync(0xFFFFFFFFu, von);   // warp lies within one point
    voff = __reduce_min_sync(0xFFFFFFFFu, voff);

    __shared__ int s_won[16], s_woff[16];
    __shared__ int s_bon[PPB], s_boff[PPB];
    int wid = tid >> 5, lane = tid & 31;
    if (lane == 0) { s_won[wid] = von; s_woff[wid] = voff; }
    __syncthreads();
    if (tid < PPB) {
        int w0 = 4 * tid;
        s_bon[tid]  = min(min(s_won[w0],  s_won[w0 + 1]),  min(s_won[w0 + 2],  s_won[w0 + 3]));
        s_boff[tid] = min(min(s_woff[w0], s_woff[w0 + 1]), min(s_woff[w0 + 2], s_woff[w0 + 3]));
    }

    // ---- Block-uniform fallback ring (P ~ 0; kept for exactness) ----
    int low = -64, high = 63;
    #pragma unroll 1
    while (true) {
        int need = 0;
        if (tid < PPB) {
            int prt = pl.x;
            int bu = (prt + high + 1 <= HH - 1) ? (high + 1) : INF_B;
            int bd = (prt + low  - 1 >= 0)      ? (1 - low)  : INF_B;
            int bound = min(bu, bd);
            if (bound < INF_B)
                need = (s_bon[tid] > bound * bound) || (s_boff[tid] > bound * bound);
        }
        if (!__syncthreads_or(need)) break;    // also syncs s_bon/s_boff
        int off2 = (slot < 64) ? (high + 1 + slot) : (low - 1 - (slot - 64));
        int r2 = pr + off2;
        int v1 = INF_I, v2 = INF_I;
        if (r2 >= 0 && r2 < HH) {
            int dn, df;
            scan_cols(hd + r2 * WW, pc, c0, dn, df);
            v1 = off2 * off2 + dn * dn;
            v2 = off2 * off2 + df * df;
        }
        v1 = __reduce_min_sync(0xFFFFFFFFu, v1);
        v2 = __reduce_min_sync(0xFFFFFFFFu, v2);
        if (lane == 0) { s_won[wid] = v1; s_woff[wid] = v2; }
        __syncthreads();
        if (tid < PPB) {
            int w0 = 4 * tid;
            s_bon[tid]  = min(s_bon[tid],
                min(min(s_won[w0],  s_won[w0 + 1]),  min(s_won[w0 + 2],  s_won[w0 + 3])));
            s_boff[tid] = min(s_boff[tid],
                min(min(s_woff[w0], s_woff[w0 + 1]), min(s_woff[w0 + 2], s_woff[w0 + 3])));
        }
        high += 64; low -= 64;
    }

    // ---- Per-point loss + block partial (warp 0 only) ----
    float partial = 0.0f;
    if (wid == 0) {
        if (tid < PPB) {
            int px = pl.x, py = pl.y;
            bool oframe = (px < 0) || (px > HH) || (py < 0) || (py > WW);
            if (!oframe) {
                bool road = (nv0 == 1.0f) || (nv1 == 1.0f) ||
                            (nv2 == 1.0f) || (nv3 == 1.0f);
                const float K1 = 21.7f;
                const float LN2_OVER_K2 = 0.69314718055994531f / 40.0f;
                partial = road ? expf(sqrtf((float)s_boff[tid]) * LN2_OVER_K2)
                               : expf(-(float)s_bon[tid] / K1);
            }
        }
        // sum lanes 0..3 into lane 0 (others contribute 0)
        partial += __shfl_xor_sync(0xFFFFFFFFu, partial, 1);
        partial += __shfl_xor_sync(0xFFFFFFFFu, partial, 2);

        if (b != 0) {
            if (lane == 0) {
                g_part[b * 32] = partial;
                __threadfence();              // partial visible before flag
                g_flag[b * 32] = 1;           // distinct 128B line per block
            }
        } else {
            // Block 0: parallel per-lane polling of distinct lines, no atomics.
            if (lane >= 1) {
                while (g_flag[lane * 32] == 0) { }
            }
            __syncwarp();
            __threadfence();                  // acquire before reading partials
            float v = (lane == 0) ? partial : g_part[lane * 32];
            #pragma unroll
            for (int o = 16; o > 0; o >>= 1)
                v += __shfl_xor_sync(0xFFFFFFFFu, v, o);
            if (lane == 0) out[0] = v * (1.0f / (float)NPTS);
            // reset flags for next graph replay (all writers observed done)
            if (lane >= 1) g_flag[lane * 32] = 0;
        }
    }
}

extern "C" void kernel_launch(void* const* d_in, const int* in_sizes, int n_in,
                              void* d_out, int out_size) {
    const float* hd  = (const float*)d_in[0];
    const int* pred  = (const int*)d_in[1];
    float* out       = (float*)d_out;
    roadloss_kernel<<<NBLK, TPB>>>(hd, pred, out);
}

// round 16
// speedup vs baseline: 1.2610x; 1.2610x over previous
#include <cuda_runtime.h>

#define HH 1024
#define WW 1024
#define NPTS 128
#define BIGD 16384        // sentinel 1D distance; BIGD^2 fits int

// One launch, one block, 1024 threads = 128 points x 8 row-slots.
// Latency/overhead-bound on one SM: minimize the serial tail — no second pred
// load, no shared handoff for mins, one barrier total, REDUX certificates.
__global__ void __launch_bounds__(1024, 1)
roadloss_kernel(const float* __restrict__ hd,
                const int*   __restrict__ pred,
                float*       __restrict__ out) {
    int tid = threadIdx.x;
    int n   = tid >> 3;           // point 0..127
    int rl  = tid & 7;            // row-slot 0..7
    bool up = (rl < 4);

    int2 p = reinterpret_cast<const int2*>(pred)[n];
    int pr = p.x;                 // component 0: vs rows in d2
    int pc = p.y;                 // component 1: vs cols in d2

    // Loss-neighbor prefetch by each group's lane 0 (same point — no extra
    // pred load). Reference indexes hd_map[py-1..py, px-1..px] with
    // px=pred[:,0]=pr, py=pred[:,1]=pc (roles swapped), JAX-clamped.
    float nv0 = 0.f, nv1 = 0.f, nv2 = 0.f, nv3 = 0.f;
    if (rl == 0) {
        int px = pr, py = pc;
        int r0 = min(max(py - 1, 0), HH - 1);
        int r1 = min(max(py,     0), HH - 1);
        int cA = min(max(px - 1, 0), WW - 1);
        int cB = min(max(px,     0), WW - 1);
        nv0 = hd[r0 * WW + cA];
        nv1 = hd[r0 * WW + cB];
        nv2 = hd[r1 * WW + cA];
        nv3 = hd[r1 * WW + cB];
    }

    unsigned int gmask = 0xFFu << (tid & 24);   // aligned 8-lane group mask

    // Aligned 8-col window containing pc.
    int c0 = (pc - 4) & ~3;
    if (c0 < 0) c0 = 0;
    if (c0 > WW - 8) c0 = WW - 8;

    int priv_on  = 0x3FFFFFFF;
    int priv_off = 0x3FFFFFFF;
    int best_on  = 0x3FFFFFFF;
    int best_off = 0x3FFFFFFF;

    // Group ring: batch j covers offsets {4j+rl} (up lanes) and {-(4j+rl-3)}
    // (down lanes). Group-uniform exit via masked REDUX certificate: all
    // unscanned rows have |dr| >= 4(j+1).
    #pragma unroll 1
    for (int j = 0; j < 256; j++) {
        int off = up ? (4 * j + rl) : -(4 * j + (rl - 3));
        int r   = pr + off;

        if (r >= 0 && r < HH) {
            const float* rowf = hd + r * WW;
            float4 a = *reinterpret_cast<const float4*>(rowf + c0);
            float4 b = *reinterpret_cast<const float4*>(rowf + c0 + 4);

            int don = BIGD, doff = BIGD;
            {
                float w[8] = {a.x, a.y, a.z, a.w, b.x, b.y, b.z, b.w};
                #pragma unroll
                for (int t = 0; t < 8; t++) {
                    int d = abs(c0 + t - pc);
                    if (w[t] != 0.0f) don = min(don, d); else doff = min(doff, d);
                }
            }
            // Lazy column extension (rare). L == 3 (mod 4), R == 0 (mod 4).
            int L = c0 - 1;
            int R = c0 + 8;
            #pragma unroll 1
            while (true) {
                int bl = (L >= 0) ? (pc - L) : 0x3FFFFFFF;
                int br = (R < WW) ? (R - pc) : 0x3FFFFFFF;
                int bound = min(bl, br);
                if (don <= bound && doff <= bound) break;
                if (bl <= br) {
                    float4 v = *reinterpret_cast<const float4*>(rowf + (L - 3));
                    float u[4] = {v.x, v.y, v.z, v.w};
                    #pragma unroll
                    for (int t = 0; t < 4; t++) {
                        int d = pc - (L - 3 + t);
                        if (u[t] != 0.0f) don = min(don, d); else doff = min(doff, d);
                    }
                    L -= 4;
                } else {
                    float4 v = *reinterpret_cast<const float4*>(rowf + R);
                    float u[4] = {v.x, v.y, v.z, v.w};
                    #pragma unroll
                    for (int t = 0; t < 4; t++) {
                        int d = (R + t) - pc;
                        if (u[t] != 0.0f) don = min(don, d); else doff = min(doff, d);
                    }
                    R += 4;
                }
            }
            int dr2 = off * off;
            priv_on  = min(priv_on,  dr2 + don * don);    // exact in int
            priv_off = min(priv_off, dr2 + doff * doff);
        }

        // Group certificate (uniform within the 8-lane group).
        best_on  = __reduce_min_sync(gmask, priv_on);
        best_off = __reduce_min_sync(gmask, priv_off);
        int nb  = 4 * (j + 1);
        int nb2 = nb * nb;
        bool stop = (best_on <= nb2) && (best_off <= nb2);
        // Exhaustion (group-uniform): all of the group's next rows OOB.
        bool exhausted = (pr + nb >= HH) && (pr - (nb + 1) < 0);
        if (stop || exhausted) break;
    }

    // ---- Per-point loss at each group's lane 0 (mins already in regs) ----
    float loss = 0.0f;
    if (rl == 0) {
        int px = pr, py = pc;
        bool outside_frame = (px < 0) || (px > HH) || (py < 0) || (py > WW);
        if (!outside_frame) {
            bool road = (nv0 == 1.0f) || (nv1 == 1.0f) ||
                        (nv2 == 1.0f) || (nv3 == 1.0f);
            const float K1 = 21.7f;
            const float LN2_OVER_K2 = 0.69314718055994531f / 40.0f;
            loss = road ? expf(sqrtf((float)best_off) * LN2_OVER_K2)
                        : expf(-(float)best_on / K1);
        }
    }

    // ---- Mean: warp sum (losses at lanes 0/8/16/24), one smem pass ----
    loss += __shfl_xor_sync(0xFFFFFFFFu, loss, 8);
    loss += __shfl_xor_sync(0xFFFFFFFFu, loss, 16);

    __shared__ float s_sum[32];
    int wid = tid >> 5, lane = tid & 31;
    if (lane == 0) s_sum[wid] = loss;
    __syncthreads();
    if (tid < 32) {
        float v = s_sum[tid];
        #pragma unroll
        for (int o = 16; o > 0; o >>= 1)
            v += __shfl_xor_sync(0xFFFFFFFFu, v, o);
        if (tid == 0) out[0] = v * (1.0f / (float)NPTS);
    }
}

extern "C" void kernel_launch(void* const* d_in, const int* in_sizes, int n_in,
                              void* d_out, int out_size) {
    const float* hd  = (const float*)d_in[0];
    const int* pred  = (const int*)d_in[1];
    float* out       = (float*)d_out;
    roadloss_kernel<<<1, 1024>>>(hd, pred, out);
}